// round 14
// baseline (speedup 1.0000x reference)
#include <cuda_runtime.h>
#include <cuda_fp16.h>
#include <cstdint>
#include <cstddef>

#define BDIM 32768
#define HDIM 512
#define KCAT 1024
#define GW ((size_t)HDIM * KCAT)
#define NCHUNK 16
#define STAGE 32768u
#define DSMEM (2 * 32768)

typedef __half h16;

__device__ h16 g_xf[(size_t)BDIM * HDIM];
__device__ h16 g_hf[(size_t)BDIM * HDIM];
__device__ h16 g_tf[(size_t)BDIM * HDIM];
__device__ h16 g_W[5 * GW];   // gates: 0=m 1=i 2=f 3=o 4=c, layout [gate][n][kcat]
__device__ h16 g_ft[(size_t)BDIM * HDIM];
__device__ h16 g_ot[(size_t)BDIM * HDIM];
__device__ h16 g_ct[(size_t)BDIM * HDIM];

__device__ __forceinline__ uint32_t smem_u32(const void* p) {
    uint32_t a;
    asm("{ .reg .u64 t; cvta.to.shared.u64 t, %1; cvt.u32.u64 %0, t; }" : "=r"(a) : "l"(p));
    return a;
}
__device__ __forceinline__ void cpa16(uint32_t dst, const void* src) {
    asm volatile("cp.async.cg.shared.global [%0], [%1], 16;" :: "r"(dst), "l"(src) : "memory");
}
__device__ __forceinline__ void ldmx4(uint32_t* d, uint32_t addr) {
    asm volatile("ldmatrix.sync.aligned.m8n8.x4.shared.b16 {%0,%1,%2,%3}, [%4];"
                 : "=r"(d[0]), "=r"(d[1]), "=r"(d[2]), "=r"(d[3]) : "r"(addr));
}
__device__ __forceinline__ void mma16816(float* c, const uint32_t* a, uint32_t b0, uint32_t b1) {
    asm volatile(
        "mma.sync.aligned.m16n8k16.row.col.f32.f16.f16.f32 "
        "{%0,%1,%2,%3}, {%4,%5,%6,%7}, {%8,%9}, {%0,%1,%2,%3};"
        : "+f"(c[0]), "+f"(c[1]), "+f"(c[2]), "+f"(c[3])
        : "r"(a[0]), "r"(a[1]), "r"(a[2]), "r"(a[3]), "r"(b0), "r"(b1));
}
__device__ __forceinline__ uint32_t swz(uint32_t off) { return off ^ ((off >> 3) & 0x70u); }
__device__ __forceinline__ float sigf(float z) { return 1.0f / (1.0f + __expf(-z)); }

// ---------------- prep ----------------
__global__ void prep_half(const float* __restrict__ s0, h16* __restrict__ d0,
                          const float* __restrict__ s1, h16* __restrict__ d1, int n4) {
    const float4* s4 = (const float4*)((blockIdx.y == 0) ? s0 : s1);
    uint32_t* d2 = (uint32_t*)((blockIdx.y == 0) ? d0 : d1);
    int stride = gridDim.x * blockDim.x;
    for (int i = blockIdx.x * blockDim.x + threadIdx.x; i < n4; i += stride) {
        float4 v = s4[i];
        __half2 p0 = __floats2half2_rn(v.x, v.y);
        __half2 p1 = __floats2half2_rn(v.z, v.w);
        d2[2 * i] = *(uint32_t*)&p0;
        d2[2 * i + 1] = *(uint32_t*)&p1;
    }
}

__global__ void prep_wt(const float* __restrict__ p0, const float* __restrict__ p1,
                        const float* __restrict__ p2, const float* __restrict__ p3,
                        const float* __restrict__ p4, const float* __restrict__ p5,
                        const float* __restrict__ p6, const float* __restrict__ p7,
                        const float* __restrict__ p8, const float* __restrict__ p9,
                        h16* __restrict__ W) {
    const float* mats[10] = {p0, p1, p2, p3, p4, p5, p6, p7, p8, p9};
    const float* src = mats[blockIdx.z];
    const int g = blockIdx.z >> 1, kh = blockIdx.z & 1;
    __shared__ float t[32][33];
    const int tx = threadIdx.x & 31, ty = threadIdx.x >> 5;
    const int k0 = blockIdx.x * 32, n0 = blockIdx.y * 32;
#pragma unroll
    for (int i = 0; i < 4; ++i)
        t[ty + i * 8][tx] = src[(size_t)(k0 + ty + i * 8) * HDIM + n0 + tx];
    __syncthreads();
#pragma unroll
    for (int i = 0; i < 4; ++i) {
        int r = ty + i * 8;
        W[(size_t)g * GW + (size_t)(n0 + r) * KCAT + kh * HDIM + k0 + tx] =
            __float2half_rn(t[tx][r]);
    }
}

// ---------------- main GEMM (exact R6 body) ----------------
// MODE 0: m-gate -> tf = half(xf * (acc + bias))            (auxh0 = xf)
// MODE 1: z<2 sigmoid / z==2 tanh -> half to o0/o1/o2
// MODE 3: i-gate: h_t = o_t * tanh(f_t*c_prev + sig(acc+b)*c_tilde) -> outi fp32
template <int MODE>
__global__ void __launch_bounds__(256, 2) k_mma(
    const h16* __restrict__ A1, const h16* __restrict__ A2,
    const h16* __restrict__ Wall, int gate0,
    const float* __restrict__ b0, const float* __restrict__ b1,
    const float* __restrict__ b2,
    h16* __restrict__ o0, h16* __restrict__ o1, h16* __restrict__ o2,
    const float* __restrict__ auxf,
    const h16* __restrict__ auxh0, const h16* __restrict__ auxh1,
    const h16* __restrict__ auxh2, const h16* __restrict__ auxh3,
    float* __restrict__ outi)
{
    extern __shared__ char sm[];
    const int tid = threadIdx.x, lane = tid & 31, wid = tid >> 5;
    const int wm = wid & 3, wn = wid >> 2;
    const int m0 = blockIdx.y * 128, n0 = blockIdx.x * 128;
    const int z = blockIdx.z;
    const h16* W = Wall + (size_t)(gate0 + z) * GW;
    const float* bias = (z == 0) ? b0 : (z == 1) ? b1 : b2;
    h16* outh = (z == 0) ? o0 : (z == 1) ? o1 : o2;

    const uint32_t sbase = smem_u32(sm);
    const int fr = tid >> 3, fsg = tid & 7;

    float acc[2][8][4];
#pragma unroll
    for (int a = 0; a < 2; ++a)
#pragma unroll
        for (int b = 0; b < 8; ++b)
#pragma unroll
            for (int c = 0; c < 4; ++c) acc[a][b][c] = 0.f;

    auto fill = [&](int c) {
        const uint32_t st = sbase + (uint32_t)(c & 1) * STAGE;
        const int kcat = c * 64;
        const h16* Ap = (kcat < HDIM) ? A1 : A2;
        const int kloc = kcat & (HDIM - 1);
#pragma unroll
        for (int i = 0; i < 4; ++i) {
            int rr = fr + i * 32;
            uint32_t off = (uint32_t)(rr * 128 + fsg * 16);
            cpa16(st + swz(off), Ap + (size_t)(m0 + rr) * HDIM + kloc + fsg * 8);
        }
#pragma unroll
        for (int i = 0; i < 4; ++i) {
            int rr = fr + i * 32;
            uint32_t off = (uint32_t)(rr * 128 + fsg * 16);
            cpa16(st + 16384u + swz(off), W + (size_t)(n0 + rr) * KCAT + kcat + fsg * 8);
        }
        asm volatile("cp.async.commit_group;" ::: "memory");
    };

    fill(0);
    for (int c = 0; c < NCHUNK; ++c) {
        if (c + 1 < NCHUNK) {
            fill(c + 1);
            asm volatile("cp.async.wait_group 1;" ::: "memory");
        } else {
            asm volatile("cp.async.wait_group 0;" ::: "memory");
        }
        __syncthreads();

        const uint32_t sA = sbase + (uint32_t)(c & 1) * STAGE;
        const uint32_t sB = sA + 16384u;
#pragma unroll
        for (int ks = 0; ks < 4; ++ks) {
            uint32_t a[2][4];
#pragma unroll
            for (int mi = 0; mi < 2; ++mi) {
                uint32_t off = (uint32_t)((wm * 32 + mi * 16 + (lane & 15)) * 128 +
                                          ks * 32 + (lane >> 4) * 16);
                ldmx4(a[mi], sA + swz(off));
            }
#pragma unroll
            for (int ni = 0; ni < 4; ++ni) {
                uint32_t b[4];
                uint32_t off = (uint32_t)((wn * 64 + ni * 16 + (lane & 15)) * 128 +
                                          ks * 32 + (lane >> 4) * 16);
                ldmx4(b, sB + swz(off));
#pragma unroll
                for (int mi = 0; mi < 2; ++mi) {
                    mma16816(acc[mi][2 * ni],     a[mi], b[0], b[2]);
                    mma16816(acc[mi][2 * ni + 1], a[mi], b[1], b[3]);
                }
            }
        }
        __syncthreads();
    }

    // -------- epilogue --------
#pragma unroll
    for (int mi = 0; mi < 2; ++mi) {
        const int rbase = m0 + wm * 32 + mi * 16 + (lane >> 2);
#pragma unroll
        for (int nj = 0; nj < 8; ++nj) {
            const int col = n0 + wn * 64 + nj * 8 + (lane & 3) * 2;
            const float bx = bias[col], by = bias[col + 1];
#pragma unroll
            for (int half = 0; half < 2; ++half) {
                const int row = rbase + half * 8;
                const size_t idx = (size_t)row * HDIM + col;
                float v0 = acc[mi][nj][2 * half] + bx;
                float v1 = acc[mi][nj][2 * half + 1] + by;
                if (MODE == 0) {
                    float2 xv = __half22float2(*(const __half2*)(auxh0 + idx));
                    __half2 p = __floats2half2_rn(xv.x * v0, xv.y * v1);
                    *(uint32_t*)(o0 + idx) = *(uint32_t*)&p;
                } else if (MODE == 1) {
                    __half2 p;
                    if (z < 2) p = __floats2half2_rn(sigf(v0), sigf(v1));
                    else       p = __floats2half2_rn(tanhf(v0), tanhf(v1));
                    *(uint32_t*)(outh + idx) = *(uint32_t*)&p;
                } else {
                    float2 cp = *(const float2*)(auxf + idx);
                    float2 ft = __half22float2(*(const __half2*)(auxh1 + idx));
                    float2 ot = __half22float2(*(const __half2*)(auxh2 + idx));
                    float2 ct = __half22float2(*(const __half2*)(auxh3 + idx));
                    float2 o;
                    o.x = ot.x * tanhf(ft.x * cp.x + sigf(v0) * ct.x);
                    o.y = ot.y * tanhf(ft.y * cp.y + sigf(v1) * ct.y);
                    *(float2*)(outi + idx) = o;
                }
            }
        }
    }
}

// ---------------- launch ----------------
extern "C" void kernel_launch(void* const* d_in, const int* in_sizes, int n_in,
                              void* d_out, int out_size) {
    const float* x = (const float*)d_in[0];
    const float* h = (const float*)d_in[1];
    const float* c = (const float*)d_in[2];
    const float* W10[10] = {(const float*)d_in[3],  (const float*)d_in[4],
                            (const float*)d_in[5],  (const float*)d_in[6],
                            (const float*)d_in[7],  (const float*)d_in[8],
                            (const float*)d_in[9],  (const float*)d_in[10],
                            (const float*)d_in[11], (const float*)d_in[12]};
    const float* bm = (const float*)d_in[13];
    const float* bi = (const float*)d_in[14];
    const float* bf = (const float*)d_in[15];
    const float* bo = (const float*)d_in[16];
    const float* bc = (const float*)d_in[17];
    float* out = (float*)d_out;

    // One-time setup (first call = correctness run, NOT captured)
    static bool init = false;
    static cudaStream_t s1;
    static cudaEvent_t eF0, eF1, eJ1, eG1;
    if (!init) {
        cudaFuncSetAttribute(k_mma<0>, cudaFuncAttributeMaxDynamicSharedMemorySize, DSMEM);
        cudaFuncSetAttribute(k_mma<1>, cudaFuncAttributeMaxDynamicSharedMemorySize, DSMEM);
        cudaFuncSetAttribute(k_mma<3>, cudaFuncAttributeMaxDynamicSharedMemorySize, DSMEM);
        cudaStreamCreateWithFlags(&s1, cudaStreamNonBlocking);
        cudaEventCreateWithFlags(&eF0, cudaEventDisableTiming);
        cudaEventCreateWithFlags(&eF1, cudaEventDisableTiming);
        cudaEventCreateWithFlags(&eJ1, cudaEventDisableTiming);
        cudaEventCreateWithFlags(&eG1, cudaEventDisableTiming);
        init = true;
    }

    h16 *xf, *hf, *tf, *Wd, *ft, *ot, *ct;
    cudaGetSymbolAddress((void**)&xf, g_xf);
    cudaGetSymbolAddress((void**)&hf, g_hf);
    cudaGetSymbolAddress((void**)&tf, g_tf);
    cudaGetSymbolAddress((void**)&Wd, g_W);
    cudaGetSymbolAddress((void**)&ft, g_ft);
    cudaGetSymbolAddress((void**)&ot, g_ot);
    cudaGetSymbolAddress((void**)&ct, g_ct);

    const int n4 = BDIM * HDIM / 4;
    dim3 g1(HDIM / 128, BDIM / 128, 1);
    dim3 g3(HDIM / 128, BDIM / 128, 3);

    // fork: prep_half (stream 0) || prep_wt (s1)
    cudaEventRecord(eF0, 0);
    cudaStreamWaitEvent(s1, eF0, 0);
    prep_half<<<dim3(1024, 2), 256>>>(x, xf, h, hf, n4);
    prep_wt<<<dim3(16, 16, 10), 256, 0, s1>>>(W10[0], W10[1], W10[2], W10[3], W10[4],
                                              W10[5], W10[6], W10[7], W10[8], W10[9], Wd);
    // join preps both ways, then fork: m (stream 0) || foc (s1)
    cudaEventRecord(eJ1, s1);
    cudaStreamWaitEvent(0, eJ1, 0);      // stream0 sees prep_wt
    cudaEventRecord(eF1, 0);
    cudaStreamWaitEvent(s1, eF1, 0);     // s1 sees prep_half

    k_mma<0><<<g1, 256, DSMEM>>>(xf, hf, Wd, 0, bm, nullptr, nullptr,
                                 tf, nullptr, nullptr,
                                 nullptr, xf, nullptr, nullptr, nullptr, nullptr);
    k_mma<1><<<g3, 256, DSMEM, s1>>>(xf, hf, Wd, 2, bf, bo, bc,
                                     ft, ot, ct,
                                     nullptr, nullptr, nullptr, nullptr, nullptr, nullptr);
    // join foc into stream 0, then i-gate
    cudaEventRecord(eG1, s1);
    cudaStreamWaitEvent(0, eG1, 0);
    k_mma<3><<<g1, 256, DSMEM>>>(tf, hf, Wd, 1, bi, nullptr, nullptr,
                                 nullptr, nullptr, nullptr,
                                 c, nullptr, ft, ot, ct, out);
}